// round 1
// baseline (speedup 1.0000x reference)
#include <cuda_runtime.h>
#include <cuda_bf16.h>
#include <cstdint>

#define N_USERS 30000
#define N_ITEMS 30000
#define N_NODES 60000
#define D 64
#define IMG_DIM 2048
#define TXT_DIM 384
#define NNZ_NORM 2000000
#define NNZ_ADJ  1000000
#define NNZ_G    150000

// ---------------- scratch (device globals; no runtime allocation) -------------
__device__ float g_egoA[N_NODES * D];
__device__ float g_egoB[N_NODES * D];
__device__ float g_cge [N_NODES * D];

__device__ float g_fv   [N_ITEMS * D];
__device__ float g_comv [N_ITEMS * D];
__device__ float g_persv[N_ITEMS * D];
__device__ float g_ft   [N_ITEMS * D];
__device__ float g_comt [N_ITEMS * D];
__device__ float g_perst[N_ITEMS * D];

__device__ float g_upv[N_USERS * D];
__device__ float g_ucv[N_USERS * D];
__device__ float g_upt[N_USERS * D];
__device__ float g_uct[N_USERS * D];

__device__ float g_pev[N_NODES * D];
__device__ float g_cev[N_NODES * D];
__device__ float g_pet[N_NODES * D];
__device__ float g_cet[N_NODES * D];

// ---------------- helpers ----------------
__device__ __forceinline__ void red_add_v4(float* addr, float4 v) {
    asm volatile("red.global.add.v4.f32 [%0], {%1,%2,%3,%4};"
                 :: "l"(addr), "f"(v.x), "f"(v.y), "f"(v.z), "f"(v.w)
                 : "memory");
}

__device__ __forceinline__ float sigmoidf_(float x) {
    return 1.0f / (1.0f + __expf(-x));
}

// ---------------- kernels ----------------

// ego = concat(user_emb, item_emb)   (vectorized float4)
__global__ void concat_kernel(const float* __restrict__ u,
                              const float* __restrict__ it,
                              float* __restrict__ out) {
    int i = blockIdx.x * blockDim.x + threadIdx.x;   // float4 index
    int n_half4 = (N_USERS * D) / 4;
    int n_tot4  = (N_NODES * D) / 4;
    if (i >= n_tot4) return;
    const float4* src = (i < n_half4) ? (const float4*)u : (const float4*)it;
    int j = (i < n_half4) ? i : (i - n_half4);
    ((float4*)out)[i] = src[j];
}

// dst += src  (float4)
__global__ void add_kernel(float* __restrict__ dst, const float* __restrict__ src, int n4) {
    int i = blockIdx.x * blockDim.x + threadIdx.x;
    if (i >= n4) return;
    float4 a = ((const float4*)dst)[i];
    float4 b = ((const float4*)src)[i];
    a.x += b.x; a.y += b.y; a.z += b.z; a.w += b.w;
    ((float4*)dst)[i] = a;
}

// out[row + row_off] += val * (colscale?colscale[col]:1) * x[col]
// 16 threads per nnz, each handles a float4 (64 floats per row).
__global__ void spmm_kernel(const int* __restrict__ rows,
                            const int* __restrict__ cols,
                            const float* __restrict__ vals,
                            const float* __restrict__ x,
                            const float* __restrict__ colscale,
                            float* __restrict__ out,
                            int nnz, int row_off) {
    long long gid = (long long)blockIdx.x * blockDim.x + threadIdx.x;
    int i = (int)(gid >> 4);
    int l = (int)(gid & 15);
    if (i >= nnz) return;
    int r = __ldg(rows + i);
    int c = __ldg(cols + i);
    float v = __ldg(vals + i);
    if (colscale) v *= __ldg(colscale + c);
    float4 xv = __ldg(((const float4*)(x + (size_t)c * D)) + l);
    float4 o;
    o.x = v * xv.x; o.y = v * xv.y; o.z = v * xv.z; o.w = v * xv.w;
    red_add_v4(out + (size_t)(r + row_off) * D + l * 4, o);
}

// C[M,64] = (A - A2?) [M,K] @ B [K,64], optional epilogue:
//   mode 0: out = acc
//   mode 1: out = sigmoid(acc + bias[n]) * F[m,n]
#define BM 64
#define BN 64
#define BK 16
__global__ void gemm_kernel(const float* __restrict__ A,
                            const float* __restrict__ A2,
                            const float* __restrict__ B,
                            const float* __restrict__ bias,
                            const float* __restrict__ F,
                            float* __restrict__ out,
                            int M, int K, int mode) {
    __shared__ float As[BK][BM];
    __shared__ float Bs[BK][BN];
    int tid = threadIdx.x;
    int m0 = blockIdx.x * BM;
    int ty = tid >> 4;        // 0..15
    int tx = tid & 15;        // 0..15
    int a_row = tid >> 2;     // 0..63
    int a_k   = (tid & 3) * 4;
    int b_k   = tid >> 4;     // 0..15
    int b_n   = (tid & 15) * 4;

    float acc[4][4] = {{0.f}};

    for (int k0 = 0; k0 < K; k0 += BK) {
        // A tile (transposed into smem)
        int gr = m0 + a_row;
        float4 av = make_float4(0.f, 0.f, 0.f, 0.f);
        if (gr < M) {
            av = *(const float4*)(A + (size_t)gr * K + k0 + a_k);
            if (A2) {
                float4 a2 = *(const float4*)(A2 + (size_t)gr * K + k0 + a_k);
                av.x -= a2.x; av.y -= a2.y; av.z -= a2.z; av.w -= a2.w;
            }
        }
        As[a_k + 0][a_row] = av.x;
        As[a_k + 1][a_row] = av.y;
        As[a_k + 2][a_row] = av.z;
        As[a_k + 3][a_row] = av.w;
        // B tile
        float4 bv = *(const float4*)(B + (size_t)(k0 + b_k) * BN + b_n);
        *(float4*)&Bs[b_k][b_n] = bv;
        __syncthreads();

        #pragma unroll
        for (int kk = 0; kk < BK; kk++) {
            float a[4], b[4];
            #pragma unroll
            for (int i = 0; i < 4; i++) a[i] = As[kk][ty * 4 + i];
            #pragma unroll
            for (int j = 0; j < 4; j++) b[j] = Bs[kk][tx * 4 + j];
            #pragma unroll
            for (int i = 0; i < 4; i++)
                #pragma unroll
                for (int j = 0; j < 4; j++)
                    acc[i][j] = fmaf(a[i], b[j], acc[i][j]);
        }
        __syncthreads();
    }

    #pragma unroll
    for (int i = 0; i < 4; i++) {
        int gm = m0 + ty * 4 + i;
        if (gm >= M) continue;
        #pragma unroll
        for (int j = 0; j < 4; j++) {
            int gn = tx * 4 + j;
            float v = acc[i][j];
            if (mode == 1) {
                v = sigmoidf_(v + __ldg(bias + gn)) * __ldg(F + (size_t)gm * 64 + gn);
            }
            out[(size_t)gm * 64 + gn] = v;
        }
    }
}

// per node row: out = cge/3 + 0.3*l2n(w0*pev+w1*pet) + 0.8*l2n(w0*cev+w1*cet)
__global__ void final_kernel(const float* __restrict__ cge,
                             const float* __restrict__ pev,
                             const float* __restrict__ pet,
                             const float* __restrict__ cev,
                             const float* __restrict__ cet,
                             const float* __restrict__ att,
                             float* __restrict__ out) {
    int warp = (blockIdx.x * blockDim.x + threadIdx.x) >> 5;
    int lane = threadIdx.x & 31;
    if (warp >= N_NODES) return;
    float a0 = __ldg(att + 0), a1 = __ldg(att + 1);
    float mx = fmaxf(a0, a1);
    float e0 = __expf(a0 - mx), e1 = __expf(a1 - mx);
    float inv = 1.0f / (e0 + e1);
    float w0 = e0 * inv, w1 = e1 * inv;

    size_t base = (size_t)warp * D;
    float p0 = w0 * pev[base + lane]      + w1 * pet[base + lane];
    float p1 = w0 * pev[base + 32 + lane] + w1 * pet[base + 32 + lane];
    float c0 = w0 * cev[base + lane]      + w1 * cet[base + lane];
    float c1 = w0 * cev[base + 32 + lane] + w1 * cet[base + 32 + lane];

    float sp = p0 * p0 + p1 * p1;
    float sc = c0 * c0 + c1 * c1;
    #pragma unroll
    for (int o = 16; o; o >>= 1) {
        sp += __shfl_xor_sync(0xffffffffu, sp, o);
        sc += __shfl_xor_sync(0xffffffffu, sc, o);
    }
    float ip = 1.0f / (sqrtf(sp) + 1e-12f);
    float ic = 1.0f / (sqrtf(sc) + 1e-12f);
    const float third = 1.0f / 3.0f;
    out[base + lane]      = cge[base + lane] * third      + 0.3f * p0 * ip + 0.8f * c0 * ic;
    out[base + 32 + lane] = cge[base + 32 + lane] * third + 0.3f * p1 * ip + 0.8f * c1 * ic;
}

// ---------------- host ----------------
static inline unsigned gdiv(long long t, int b) { return (unsigned)((t + b - 1) / b); }

extern "C" void kernel_launch(void* const* d_in, const int* in_sizes, int n_in,
                              void* d_out, int out_size) {
    const float* user_emb    = (const float*)d_in[0];
    const float* item_emb    = (const float*)d_in[1];
    const float* image_feats = (const float*)d_in[2];
    const float* text_feats  = (const float*)d_in[3];
    const float* trs_v       = (const float*)d_in[4];
    const float* trs_t       = (const float*)d_in[5];
    const float* gate_v      = (const float*)d_in[6];
    const float* gate1_v     = (const float*)d_in[7];
    const float* gate_t      = (const float*)d_in[8];
    const float* gate1_t     = (const float*)d_in[9];
    const float* bias_v      = (const float*)d_in[10];
    const float* bias1_v     = (const float*)d_in[11];
    const float* bias_t      = (const float*)d_in[12];
    const float* bias1_t     = (const float*)d_in[13];
    const float* att         = (const float*)d_in[14];
    const float* num_inters  = (const float*)d_in[15];
    const float* vals_norm   = (const float*)d_in[16];
    const float* vals_adj    = (const float*)d_in[17];
    const float* vals_img_ii = (const float*)d_in[18];
    const float* vals_txt_ii = (const float*)d_in[19];
    const float* vals_img_uu = (const float*)d_in[20];
    const float* vals_txt_uu = (const float*)d_in[21];
    const float* vals_cii    = (const float*)d_in[22];
    const float* vals_cuu    = (const float*)d_in[23];
    const int* idx_norm      = (const int*)d_in[24];
    const int* idx_adj       = (const int*)d_in[25];
    const int* idx_img_ii    = (const int*)d_in[26];
    const int* idx_txt_ii    = (const int*)d_in[27];
    const int* idx_img_uu    = (const int*)d_in[28];
    const int* idx_txt_uu    = (const int*)d_in[29];
    const int* idx_cii       = (const int*)d_in[30];
    const int* idx_cuu       = (const int*)d_in[31];
    float* out = (float*)d_out;

    float *egoA, *egoB, *cge, *fv, *comv, *persv, *ft, *comt, *perst;
    float *upv, *ucv, *upt, *uct, *pev, *cev, *pet, *cet;
    cudaGetSymbolAddress((void**)&egoA,  g_egoA);
    cudaGetSymbolAddress((void**)&egoB,  g_egoB);
    cudaGetSymbolAddress((void**)&cge,   g_cge);
    cudaGetSymbolAddress((void**)&fv,    g_fv);
    cudaGetSymbolAddress((void**)&comv,  g_comv);
    cudaGetSymbolAddress((void**)&persv, g_persv);
    cudaGetSymbolAddress((void**)&ft,    g_ft);
    cudaGetSymbolAddress((void**)&comt,  g_comt);
    cudaGetSymbolAddress((void**)&perst, g_perst);
    cudaGetSymbolAddress((void**)&upv,   g_upv);
    cudaGetSymbolAddress((void**)&ucv,   g_ucv);
    cudaGetSymbolAddress((void**)&upt,   g_upt);
    cudaGetSymbolAddress((void**)&uct,   g_uct);
    cudaGetSymbolAddress((void**)&pev,   g_pev);
    cudaGetSymbolAddress((void**)&cev,   g_cev);
    cudaGetSymbolAddress((void**)&pet,   g_pet);
    cudaGetSymbolAddress((void**)&cet,   g_cet);

    const size_t NB_NODES = (size_t)N_NODES * D * sizeof(float);
    const size_t NB_HALF  = (size_t)N_USERS * D * sizeof(float);
    const int n4_nodes = N_NODES * D / 4;

    // ---- CGE: 3 propagation layers over norm adjacency ----
    concat_kernel<<<gdiv(n4_nodes, 256), 256>>>(user_emb, item_emb, egoA);
    cudaMemsetAsync(cge, 0, NB_NODES, 0);

    cudaMemsetAsync(egoB, 0, NB_NODES, 0);
    spmm_kernel<<<gdiv((long long)NNZ_NORM * 16, 256), 256>>>(
        idx_norm, idx_norm + NNZ_NORM, vals_norm, egoA, nullptr, egoB, NNZ_NORM, 0);
    add_kernel<<<gdiv(n4_nodes, 256), 256>>>(cge, egoB, n4_nodes);

    cudaMemsetAsync(egoA, 0, NB_NODES, 0);
    spmm_kernel<<<gdiv((long long)NNZ_NORM * 16, 256), 256>>>(
        idx_norm, idx_norm + NNZ_NORM, vals_norm, egoB, nullptr, egoA, NNZ_NORM, 0);
    add_kernel<<<gdiv(n4_nodes, 256), 256>>>(cge, egoA, n4_nodes);

    cudaMemsetAsync(egoB, 0, NB_NODES, 0);
    spmm_kernel<<<gdiv((long long)NNZ_NORM * 16, 256), 256>>>(
        idx_norm, idx_norm + NNZ_NORM, vals_norm, egoA, nullptr, egoB, NNZ_NORM, 0);
    add_kernel<<<gdiv(n4_nodes, 256), 256>>>(cge, egoB, n4_nodes);

    // ---- gating (dense GEMMs) ----
    unsigned gblk = gdiv(N_ITEMS, BM);
    gemm_kernel<<<gblk, 256>>>(image_feats, nullptr, trs_v, nullptr, nullptr, fv,   N_ITEMS, IMG_DIM, 0);
    gemm_kernel<<<gblk, 256>>>(fv, nullptr, gate_v,  bias_v,  fv, comv,  N_ITEMS, 64, 1);
    gemm_kernel<<<gblk, 256>>>(fv, comv,    gate1_v, bias1_v, fv, persv, N_ITEMS, 64, 1);
    gemm_kernel<<<gblk, 256>>>(text_feats, nullptr, trs_t, nullptr, nullptr, ft,   N_ITEMS, TXT_DIM, 0);
    gemm_kernel<<<gblk, 256>>>(ft, nullptr, gate_t,  bias_t,  ft, comt,  N_ITEMS, 64, 1);
    gemm_kernel<<<gblk, 256>>>(ft, comt,    gate1_t, bias1_t, ft, perst, N_ITEMS, 64, 1);

    // ---- u_pers / u_com via adjacency (inv_u folded into next spmm as colscale) ----
    cudaMemsetAsync(upv, 0, NB_HALF, 0);
    cudaMemsetAsync(ucv, 0, NB_HALF, 0);
    cudaMemsetAsync(upt, 0, NB_HALF, 0);
    cudaMemsetAsync(uct, 0, NB_HALF, 0);
    unsigned gadj = gdiv((long long)NNZ_ADJ * 16, 256);
    spmm_kernel<<<gadj, 256>>>(idx_adj, idx_adj + NNZ_ADJ, vals_adj, persv, nullptr, upv, NNZ_ADJ, 0);
    spmm_kernel<<<gadj, 256>>>(idx_adj, idx_adj + NNZ_ADJ, vals_adj, comv,  nullptr, ucv, NNZ_ADJ, 0);
    spmm_kernel<<<gadj, 256>>>(idx_adj, idx_adj + NNZ_ADJ, vals_adj, perst, nullptr, upt, NNZ_ADJ, 0);
    spmm_kernel<<<gadj, 256>>>(idx_adj, idx_adj + NNZ_ADJ, vals_adj, comt,  nullptr, uct, NNZ_ADJ, 0);

    // ---- modal graph embeddings ----
    cudaMemsetAsync(pev, 0, NB_NODES, 0);
    cudaMemsetAsync(cev, 0, NB_NODES, 0);
    cudaMemsetAsync(pet, 0, NB_NODES, 0);
    cudaMemsetAsync(cet, 0, NB_NODES, 0);
    unsigned gg = gdiv((long long)NNZ_G * 16, 256);
    // users block (uu graphs; colscale = inv_u = num_inters[:30000])
    spmm_kernel<<<gg, 256>>>(idx_img_uu, idx_img_uu + NNZ_G, vals_img_uu, upv, num_inters, pev, NNZ_G, 0);
    spmm_kernel<<<gg, 256>>>(idx_cuu,    idx_cuu    + NNZ_G, vals_cuu,    ucv, num_inters, cev, NNZ_G, 0);
    spmm_kernel<<<gg, 256>>>(idx_txt_uu, idx_txt_uu + NNZ_G, vals_txt_uu, upt, num_inters, pet, NNZ_G, 0);
    spmm_kernel<<<gg, 256>>>(idx_cuu,    idx_cuu    + NNZ_G, vals_cuu,    uct, num_inters, cet, NNZ_G, 0);
    // items block (ii graphs)
    spmm_kernel<<<gg, 256>>>(idx_img_ii, idx_img_ii + NNZ_G, vals_img_ii, persv, nullptr, pev, NNZ_G, N_USERS);
    spmm_kernel<<<gg, 256>>>(idx_cii,    idx_cii    + NNZ_G, vals_cii,    comv,  nullptr, cev, NNZ_G, N_USERS);
    spmm_kernel<<<gg, 256>>>(idx_txt_ii, idx_txt_ii + NNZ_G, vals_txt_ii, perst, nullptr, pet, NNZ_G, N_USERS);
    spmm_kernel<<<gg, 256>>>(idx_cii,    idx_cii    + NNZ_G, vals_cii,    comt,  nullptr, cet, NNZ_G, N_USERS);

    // ---- final fuse ----
    final_kernel<<<gdiv((long long)N_NODES * 32, 256), 256>>>(cge, pev, pet, cev, cet, att, out);
}

// round 2
// speedup vs baseline: 1.2960x; 1.2960x over previous
#include <cuda_runtime.h>
#include <cuda_bf16.h>
#include <cstdint>

#define N_USERS 30000
#define N_ITEMS 30000
#define N_NODES 60000
#define D 64
#define IMG_DIM 2048
#define TXT_DIM 384
#define NNZ_NORM 2000000
#define NNZ_ADJ  1000000
#define NNZ_G    150000
#define NNZ_TOT  3900000

// segment starts in concatenated nnz space: norm, adj, img_ii, txt_ii, img_uu, txt_uu, cii, cuu
#define SEG_NORM   0
#define SEG_ADJ    2000000
#define SEG_IMG_II 3000000
#define SEG_TXT_II 3150000
#define SEG_IMG_UU 3300000
#define SEG_TXT_UU 3450000
#define SEG_CII    3600000
#define SEG_CUU    3750000

// rowptr offsets (rows+1 per matrix): norm 60001, others 30001
#define RPO_NORM   0
#define RPO_ADJ    60001
#define RPO_IMG_II 90002
#define RPO_TXT_II 120003
#define RPO_IMG_UU 150004
#define RPO_TXT_UU 180005
#define RPO_CII    210006
#define RPO_CUU    240007
#define RP_TOTAL   270008

// ---------------- scratch (device globals; no runtime allocation) -------------
__device__ float g_egoA[N_NODES * D];
__device__ float g_egoB[N_NODES * D];
__device__ float g_cge [N_NODES * D];

__device__ float g_fv   [N_ITEMS * D];
__device__ float g_comv [N_ITEMS * D];
__device__ float g_persv[N_ITEMS * D];
__device__ float g_ft   [N_ITEMS * D];
__device__ float g_comt [N_ITEMS * D];
__device__ float g_perst[N_ITEMS * D];

__device__ float g_upv[N_USERS * D];
__device__ float g_ucv[N_USERS * D];
__device__ float g_upt[N_USERS * D];
__device__ float g_uct[N_USERS * D];

__device__ float g_pev[N_NODES * D];
__device__ float g_cev[N_NODES * D];
__device__ float g_pet[N_NODES * D];
__device__ float g_cet[N_NODES * D];

// CSR scratch
__device__ int   g_counts[RP_TOTAL];
__device__ int   g_rowptr[RP_TOTAL];
__device__ int   g_cursor[RP_TOTAL];
__device__ int   g_colss [NNZ_TOT];
__device__ float g_valss [NNZ_TOT];

__constant__ int c_nrows[8] = {60000,30000,30000,30000,30000,30000,30000,30000};
__constant__ int c_rpoff[8] = {RPO_NORM,RPO_ADJ,RPO_IMG_II,RPO_TXT_II,RPO_IMG_UU,RPO_TXT_UU,RPO_CII,RPO_CUU};

// ---------------- helpers ----------------
__device__ __forceinline__ float sigmoidf_(float x) {
    return 1.0f / (1.0f + __expf(-x));
}

// ---------------- CSR build ----------------
__global__ void hist_kernel(const int* __restrict__ i0, const int* __restrict__ i1,
                            const int* __restrict__ i2, const int* __restrict__ i3,
                            const int* __restrict__ i4, const int* __restrict__ i5,
                            const int* __restrict__ i6, const int* __restrict__ i7,
                            int* __restrict__ counts) {
    int gid = blockIdx.x * blockDim.x + threadIdx.x;
    if (gid >= NNZ_TOT) return;
    const int* rows; int i, rpo;
    if      (gid < SEG_ADJ)    { rows = i0; i = gid - SEG_NORM;   rpo = RPO_NORM;   }
    else if (gid < SEG_IMG_II) { rows = i1; i = gid - SEG_ADJ;    rpo = RPO_ADJ;    }
    else if (gid < SEG_TXT_II) { rows = i2; i = gid - SEG_IMG_II; rpo = RPO_IMG_II; }
    else if (gid < SEG_IMG_UU) { rows = i3; i = gid - SEG_TXT_II; rpo = RPO_TXT_II; }
    else if (gid < SEG_TXT_UU) { rows = i4; i = gid - SEG_IMG_UU; rpo = RPO_IMG_UU; }
    else if (gid < SEG_CII)    { rows = i5; i = gid - SEG_TXT_UU; rpo = RPO_TXT_UU; }
    else if (gid < SEG_CUU)    { rows = i6; i = gid - SEG_CII;    rpo = RPO_CII;    }
    else                       { rows = i7; i = gid - SEG_CUU;    rpo = RPO_CUU;    }
    atomicAdd(&counts[rpo + __ldg(rows + i)], 1);
}

// one block per matrix; exclusive prefix sum of counts -> rowptr
__global__ void scan_kernel(const int* __restrict__ counts, int* __restrict__ rowptr) {
    int m = blockIdx.x;
    int n = c_nrows[m];
    const int* cnt = counts + c_rpoff[m];
    int* rp = rowptr + c_rpoff[m];
    __shared__ int part[1024];
    int tid = threadIdx.x;
    int chunk = (n + 1023) >> 10;
    int lo = tid * chunk;
    int hi = lo + chunk; if (hi > n) hi = n;
    int s = 0;
    for (int i = lo; i < hi; i++) s += cnt[i];
    part[tid] = s;
    __syncthreads();
    for (int off = 1; off < 1024; off <<= 1) {
        int v = (tid >= off) ? part[tid - off] : 0;
        __syncthreads();
        part[tid] += v;
        __syncthreads();
    }
    int base = (tid == 0) ? 0 : part[tid - 1];
    for (int i = lo; i < hi; i++) { rp[i] = base; base += cnt[i]; }
    if (lo < n && hi == n) rp[n] = base;
}

__global__ void scatter_kernel(const int* __restrict__ i0, const int* __restrict__ i1,
                               const int* __restrict__ i2, const int* __restrict__ i3,
                               const int* __restrict__ i4, const int* __restrict__ i5,
                               const int* __restrict__ i6, const int* __restrict__ i7,
                               const float* __restrict__ v0, const float* __restrict__ v1,
                               const float* __restrict__ v2, const float* __restrict__ v3,
                               const float* __restrict__ v4, const float* __restrict__ v5,
                               const float* __restrict__ v6, const float* __restrict__ v7,
                               const float* __restrict__ num_inters,
                               int* __restrict__ cursor,
                               int* __restrict__ cols_s, float* __restrict__ vals_s) {
    int gid = blockIdx.x * blockDim.x + threadIdx.x;
    if (gid >= NNZ_TOT) return;
    const int* idx; const float* vls; int i, rpo, seg, nz; bool sc;
    if      (gid < SEG_ADJ)    { idx=i0; vls=v0; i=gid-SEG_NORM;   rpo=RPO_NORM;   seg=SEG_NORM;   nz=NNZ_NORM; sc=false; }
    else if (gid < SEG_IMG_II) { idx=i1; vls=v1; i=gid-SEG_ADJ;    rpo=RPO_ADJ;    seg=SEG_ADJ;    nz=NNZ_ADJ;  sc=false; }
    else if (gid < SEG_TXT_II) { idx=i2; vls=v2; i=gid-SEG_IMG_II; rpo=RPO_IMG_II; seg=SEG_IMG_II; nz=NNZ_G;    sc=false; }
    else if (gid < SEG_IMG_UU) { idx=i3; vls=v3; i=gid-SEG_TXT_II; rpo=RPO_TXT_II; seg=SEG_TXT_II; nz=NNZ_G;    sc=false; }
    else if (gid < SEG_TXT_UU) { idx=i4; vls=v4; i=gid-SEG_IMG_UU; rpo=RPO_IMG_UU; seg=SEG_IMG_UU; nz=NNZ_G;    sc=true;  }
    else if (gid < SEG_CII)    { idx=i5; vls=v5; i=gid-SEG_TXT_UU; rpo=RPO_TXT_UU; seg=SEG_TXT_UU; nz=NNZ_G;    sc=true;  }
    else if (gid < SEG_CUU)    { idx=i6; vls=v6; i=gid-SEG_CII;    rpo=RPO_CII;    seg=SEG_CII;    nz=NNZ_G;    sc=false; }
    else                       { idx=i7; vls=v7; i=gid-SEG_CUU;    rpo=RPO_CUU;    seg=SEG_CUU;    nz=NNZ_G;    sc=true;  }
    int r = __ldg(idx + i);
    int c = __ldg(idx + nz + i);
    float v = __ldg(vls + i);
    if (sc) v *= __ldg(num_inters + c);   // fold inv_u colscale into uu-matrix values
    int pos = atomicAdd(&cursor[rpo + r], 1);
    cols_s[seg + pos] = c;
    vals_s[seg + pos] = v;
}

// ---------------- compute kernels ----------------

// ego = concat(user_emb, item_emb)
__global__ void concat_kernel(const float* __restrict__ u,
                              const float* __restrict__ it,
                              float* __restrict__ out) {
    int i = blockIdx.x * blockDim.x + threadIdx.x;
    int n_half4 = (N_USERS * D) / 4;
    int n_tot4  = (N_NODES * D) / 4;
    if (i >= n_tot4) return;
    const float4* src = (i < n_half4) ? (const float4*)u : (const float4*)it;
    int j = (i < n_half4) ? i : (i - n_half4);
    ((float4*)out)[i] = src[j];
}

// CSR SpMM, single channel. 16 threads per row; each lane holds one float4 (D=64).
// mode: 0 = just store; 1 = store + cge = acc; 2 = store + cge += acc
__global__ void spmm1_kernel(const int* __restrict__ rowptr,
                             const int* __restrict__ cols,
                             const float* __restrict__ vals,
                             const float* __restrict__ x,
                             float* __restrict__ o,
                             float* __restrict__ cge,
                             int mode, int n_rows, int row_off) {
    int t = blockIdx.x * blockDim.x + threadIdx.x;
    int row = t >> 4, lane = t & 15;
    if (row >= n_rows) return;
    int start = __ldg(rowptr + row), end = __ldg(rowptr + row + 1);
    float4 a0 = make_float4(0.f,0.f,0.f,0.f);
    float4 a1 = make_float4(0.f,0.f,0.f,0.f);
    int k = start;
    for (; k + 2 <= end; k += 2) {
        int   c0 = __ldg(cols + k);
        int   c1 = __ldg(cols + k + 1);
        float w0 = __ldg(vals + k);
        float w1 = __ldg(vals + k + 1);
        float4 p0 = __ldg((const float4*)(x + (size_t)c0 * D) + lane);
        float4 p1 = __ldg((const float4*)(x + (size_t)c1 * D) + lane);
        a0.x = fmaf(w0, p0.x, a0.x); a0.y = fmaf(w0, p0.y, a0.y);
        a0.z = fmaf(w0, p0.z, a0.z); a0.w = fmaf(w0, p0.w, a0.w);
        a1.x = fmaf(w1, p1.x, a1.x); a1.y = fmaf(w1, p1.y, a1.y);
        a1.z = fmaf(w1, p1.z, a1.z); a1.w = fmaf(w1, p1.w, a1.w);
    }
    if (k < end) {
        int   c0 = __ldg(cols + k);
        float w0 = __ldg(vals + k);
        float4 p0 = __ldg((const float4*)(x + (size_t)c0 * D) + lane);
        a0.x = fmaf(w0, p0.x, a0.x); a0.y = fmaf(w0, p0.y, a0.y);
        a0.z = fmaf(w0, p0.z, a0.z); a0.w = fmaf(w0, p0.w, a0.w);
    }
    a0.x += a1.x; a0.y += a1.y; a0.z += a1.z; a0.w += a1.w;
    size_t obase = (size_t)(row + row_off) * D;
    ((float4*)(o + obase))[lane] = a0;
    if (mode == 1) {
        ((float4*)(cge + obase))[lane] = a0;
    } else if (mode == 2) {
        float4 t4 = ((float4*)(cge + obase))[lane];
        t4.x += a0.x; t4.y += a0.y; t4.z += a0.z; t4.w += a0.w;
        ((float4*)(cge + obase))[lane] = t4;
    }
}

// CSR SpMM fused over 2 channels (same sparsity, two dense inputs/outputs)
__global__ void spmm2_kernel(const int* __restrict__ rowptr,
                             const int* __restrict__ cols,
                             const float* __restrict__ vals,
                             const float* __restrict__ x0, const float* __restrict__ x1,
                             float* __restrict__ o0, float* __restrict__ o1,
                             int n_rows, int row_off) {
    int t = blockIdx.x * blockDim.x + threadIdx.x;
    int row = t >> 4, lane = t & 15;
    if (row >= n_rows) return;
    int start = __ldg(rowptr + row), end = __ldg(rowptr + row + 1);
    float4 a0 = make_float4(0.f,0.f,0.f,0.f);
    float4 a1 = make_float4(0.f,0.f,0.f,0.f);
    for (int k = start; k < end; k++) {
        int   c = __ldg(cols + k);
        float w = __ldg(vals + k);
        size_t off = (size_t)c * D;
        float4 p0 = __ldg((const float4*)(x0 + off) + lane);
        float4 p1 = __ldg((const float4*)(x1 + off) + lane);
        a0.x = fmaf(w, p0.x, a0.x); a0.y = fmaf(w, p0.y, a0.y);
        a0.z = fmaf(w, p0.z, a0.z); a0.w = fmaf(w, p0.w, a0.w);
        a1.x = fmaf(w, p1.x, a1.x); a1.y = fmaf(w, p1.y, a1.y);
        a1.z = fmaf(w, p1.z, a1.z); a1.w = fmaf(w, p1.w, a1.w);
    }
    size_t obase = (size_t)(row + row_off) * D;
    ((float4*)(o0 + obase))[lane] = a0;
    ((float4*)(o1 + obase))[lane] = a1;
}

// CSR SpMM fused over 4 channels (adjacency: persv/comv/perst/comt -> upv/ucv/upt/uct)
__global__ void spmm4_kernel(const int* __restrict__ rowptr,
                             const int* __restrict__ cols,
                             const float* __restrict__ vals,
                             const float* __restrict__ x0, const float* __restrict__ x1,
                             const float* __restrict__ x2, const float* __restrict__ x3,
                             float* __restrict__ o0, float* __restrict__ o1,
                             float* __restrict__ o2, float* __restrict__ o3,
                             int n_rows) {
    int t = blockIdx.x * blockDim.x + threadIdx.x;
    int row = t >> 4, lane = t & 15;
    if (row >= n_rows) return;
    int start = __ldg(rowptr + row), end = __ldg(rowptr + row + 1);
    float4 a0 = make_float4(0.f,0.f,0.f,0.f);
    float4 a1 = make_float4(0.f,0.f,0.f,0.f);
    float4 a2 = make_float4(0.f,0.f,0.f,0.f);
    float4 a3 = make_float4(0.f,0.f,0.f,0.f);
    for (int k = start; k < end; k++) {
        int   c = __ldg(cols + k);
        float w = __ldg(vals + k);
        size_t off = (size_t)c * D;
        float4 p0 = __ldg((const float4*)(x0 + off) + lane);
        float4 p1 = __ldg((const float4*)(x1 + off) + lane);
        float4 p2 = __ldg((const float4*)(x2 + off) + lane);
        float4 p3 = __ldg((const float4*)(x3 + off) + lane);
        a0.x = fmaf(w, p0.x, a0.x); a0.y = fmaf(w, p0.y, a0.y);
        a0.z = fmaf(w, p0.z, a0.z); a0.w = fmaf(w, p0.w, a0.w);
        a1.x = fmaf(w, p1.x, a1.x); a1.y = fmaf(w, p1.y, a1.y);
        a1.z = fmaf(w, p1.z, a1.z); a1.w = fmaf(w, p1.w, a1.w);
        a2.x = fmaf(w, p2.x, a2.x); a2.y = fmaf(w, p2.y, a2.y);
        a2.z = fmaf(w, p2.z, a2.z); a2.w = fmaf(w, p2.w, a2.w);
        a3.x = fmaf(w, p3.x, a3.x); a3.y = fmaf(w, p3.y, a3.y);
        a3.z = fmaf(w, p3.z, a3.z); a3.w = fmaf(w, p3.w, a3.w);
    }
    size_t obase = (size_t)row * D;
    ((float4*)(o0 + obase))[lane] = a0;
    ((float4*)(o1 + obase))[lane] = a1;
    ((float4*)(o2 + obase))[lane] = a2;
    ((float4*)(o3 + obase))[lane] = a3;
}

// C[M,64] = (A - A2?) [M,K] @ B [K,64]; mode1: out = sigmoid(acc + bias[n]) * F[m,n]
#define BM 64
#define BN 64
#define BK 16
__global__ void gemm_kernel(const float* __restrict__ A,
                            const float* __restrict__ A2,
                            const float* __restrict__ B,
                            const float* __restrict__ bias,
                            const float* __restrict__ F,
                            float* __restrict__ out,
                            int M, int K, int mode) {
    __shared__ float As[BK][BM];
    __shared__ float Bs[BK][BN];
    int tid = threadIdx.x;
    int m0 = blockIdx.x * BM;
    int ty = tid >> 4;
    int tx = tid & 15;
    int a_row = tid >> 2;
    int a_k   = (tid & 3) * 4;
    int b_k   = tid >> 4;
    int b_n   = (tid & 15) * 4;

    float acc[4][4] = {{0.f}};

    for (int k0 = 0; k0 < K; k0 += BK) {
        int gr = m0 + a_row;
        float4 av = make_float4(0.f, 0.f, 0.f, 0.f);
        if (gr < M) {
            av = *(const float4*)(A + (size_t)gr * K + k0 + a_k);
            if (A2) {
                float4 a2 = *(const float4*)(A2 + (size_t)gr * K + k0 + a_k);
                av.x -= a2.x; av.y -= a2.y; av.z -= a2.z; av.w -= a2.w;
            }
        }
        As[a_k + 0][a_row] = av.x;
        As[a_k + 1][a_row] = av.y;
        As[a_k + 2][a_row] = av.z;
        As[a_k + 3][a_row] = av.w;
        float4 bv = *(const float4*)(B + (size_t)(k0 + b_k) * BN + b_n);
        *(float4*)&Bs[b_k][b_n] = bv;
        __syncthreads();

        #pragma unroll
        for (int kk = 0; kk < BK; kk++) {
            float a[4], b[4];
            #pragma unroll
            for (int i = 0; i < 4; i++) a[i] = As[kk][ty * 4 + i];
            #pragma unroll
            for (int j = 0; j < 4; j++) b[j] = Bs[kk][tx * 4 + j];
            #pragma unroll
            for (int i = 0; i < 4; i++)
                #pragma unroll
                for (int j = 0; j < 4; j++)
                    acc[i][j] = fmaf(a[i], b[j], acc[i][j]);
        }
        __syncthreads();
    }

    #pragma unroll
    for (int i = 0; i < 4; i++) {
        int gm = m0 + ty * 4 + i;
        if (gm >= M) continue;
        #pragma unroll
        for (int j = 0; j < 4; j++) {
            int gn = tx * 4 + j;
            float v = acc[i][j];
            if (mode == 1) {
                v = sigmoidf_(v + __ldg(bias + gn)) * __ldg(F + (size_t)gm * 64 + gn);
            }
            out[(size_t)gm * 64 + gn] = v;
        }
    }
}

// per node row: out = cge/3 + 0.3*l2n(w0*pev+w1*pet) + 0.8*l2n(w0*cev+w1*cet)
__global__ void final_kernel(const float* __restrict__ cge,
                             const float* __restrict__ pev,
                             const float* __restrict__ pet,
                             const float* __restrict__ cev,
                             const float* __restrict__ cet,
                             const float* __restrict__ att,
                             float* __restrict__ out) {
    int warp = (blockIdx.x * blockDim.x + threadIdx.x) >> 5;
    int lane = threadIdx.x & 31;
    if (warp >= N_NODES) return;
    float a0 = __ldg(att + 0), a1 = __ldg(att + 1);
    float mx = fmaxf(a0, a1);
    float e0 = __expf(a0 - mx), e1 = __expf(a1 - mx);
    float inv = 1.0f / (e0 + e1);
    float w0 = e0 * inv, w1 = e1 * inv;

    size_t base = (size_t)warp * D;
    float p0 = w0 * pev[base + lane]      + w1 * pet[base + lane];
    float p1 = w0 * pev[base + 32 + lane] + w1 * pet[base + 32 + lane];
    float c0 = w0 * cev[base + lane]      + w1 * cet[base + lane];
    float c1 = w0 * cev[base + 32 + lane] + w1 * cet[base + 32 + lane];

    float sp = p0 * p0 + p1 * p1;
    float sc = c0 * c0 + c1 * c1;
    #pragma unroll
    for (int o = 16; o; o >>= 1) {
        sp += __shfl_xor_sync(0xffffffffu, sp, o);
        sc += __shfl_xor_sync(0xffffffffu, sc, o);
    }
    float ip = 1.0f / (sqrtf(sp) + 1e-12f);
    float ic = 1.0f / (sqrtf(sc) + 1e-12f);
    const float third = 1.0f / 3.0f;
    out[base + lane]      = cge[base + lane] * third      + 0.3f * p0 * ip + 0.8f * c0 * ic;
    out[base + 32 + lane] = cge[base + 32 + lane] * third + 0.3f * p1 * ip + 0.8f * c1 * ic;
}

// ---------------- host ----------------
static inline unsigned gdiv(long long t, int b) { return (unsigned)((t + b - 1) / b); }

extern "C" void kernel_launch(void* const* d_in, const int* in_sizes, int n_in,
                              void* d_out, int out_size) {
    const float* user_emb    = (const float*)d_in[0];
    const float* item_emb    = (const float*)d_in[1];
    const float* image_feats = (const float*)d_in[2];
    const float* text_feats  = (const float*)d_in[3];
    const float* trs_v       = (const float*)d_in[4];
    const float* trs_t       = (const float*)d_in[5];
    const float* gate_v      = (const float*)d_in[6];
    const float* gate1_v     = (const float*)d_in[7];
    const float* gate_t      = (const float*)d_in[8];
    const float* gate1_t     = (const float*)d_in[9];
    const float* bias_v      = (const float*)d_in[10];
    const float* bias1_v     = (const float*)d_in[11];
    const float* bias_t      = (const float*)d_in[12];
    const float* bias1_t     = (const float*)d_in[13];
    const float* att         = (const float*)d_in[14];
    const float* num_inters  = (const float*)d_in[15];
    const float* vals_norm   = (const float*)d_in[16];
    const float* vals_adj    = (const float*)d_in[17];
    const float* vals_img_ii = (const float*)d_in[18];
    const float* vals_txt_ii = (const float*)d_in[19];
    const float* vals_img_uu = (const float*)d_in[20];
    const float* vals_txt_uu = (const float*)d_in[21];
    const float* vals_cii    = (const float*)d_in[22];
    const float* vals_cuu    = (const float*)d_in[23];
    const int* idx_norm      = (const int*)d_in[24];
    const int* idx_adj       = (const int*)d_in[25];
    const int* idx_img_ii    = (const int*)d_in[26];
    const int* idx_txt_ii    = (const int*)d_in[27];
    const int* idx_img_uu    = (const int*)d_in[28];
    const int* idx_txt_uu    = (const int*)d_in[29];
    const int* idx_cii       = (const int*)d_in[30];
    const int* idx_cuu       = (const int*)d_in[31];
    float* out = (float*)d_out;

    float *egoA, *egoB, *cge, *fv, *comv, *persv, *ft, *comt, *perst;
    float *upv, *ucv, *upt, *uct, *pev, *cev, *pet, *cet;
    int *counts, *rowptr, *cursor, *colss; float* valss;
    cudaGetSymbolAddress((void**)&egoA,  g_egoA);
    cudaGetSymbolAddress((void**)&egoB,  g_egoB);
    cudaGetSymbolAddress((void**)&cge,   g_cge);
    cudaGetSymbolAddress((void**)&fv,    g_fv);
    cudaGetSymbolAddress((void**)&comv,  g_comv);
    cudaGetSymbolAddress((void**)&persv, g_persv);
    cudaGetSymbolAddress((void**)&ft,    g_ft);
    cudaGetSymbolAddress((void**)&comt,  g_comt);
    cudaGetSymbolAddress((void**)&perst, g_perst);
    cudaGetSymbolAddress((void**)&upv,   g_upv);
    cudaGetSymbolAddress((void**)&ucv,   g_ucv);
    cudaGetSymbolAddress((void**)&upt,   g_upt);
    cudaGetSymbolAddress((void**)&uct,   g_uct);
    cudaGetSymbolAddress((void**)&pev,   g_pev);
    cudaGetSymbolAddress((void**)&cev,   g_cev);
    cudaGetSymbolAddress((void**)&pet,   g_pet);
    cudaGetSymbolAddress((void**)&cet,   g_cet);
    cudaGetSymbolAddress((void**)&counts, g_counts);
    cudaGetSymbolAddress((void**)&rowptr, g_rowptr);
    cudaGetSymbolAddress((void**)&cursor, g_cursor);
    cudaGetSymbolAddress((void**)&colss,  g_colss);
    cudaGetSymbolAddress((void**)&valss,  g_valss);

    const int n4_nodes = N_NODES * D / 4;

    // ---- CSR build for all 8 matrices ----
    cudaMemsetAsync(counts, 0, RP_TOTAL * sizeof(int), 0);
    hist_kernel<<<gdiv(NNZ_TOT, 256), 256>>>(idx_norm, idx_adj, idx_img_ii, idx_txt_ii,
                                             idx_img_uu, idx_txt_uu, idx_cii, idx_cuu, counts);
    scan_kernel<<<8, 1024>>>(counts, rowptr);
    cudaMemcpyAsync(cursor, rowptr, RP_TOTAL * sizeof(int), cudaMemcpyDeviceToDevice, 0);
    scatter_kernel<<<gdiv(NNZ_TOT, 256), 256>>>(idx_norm, idx_adj, idx_img_ii, idx_txt_ii,
                                                idx_img_uu, idx_txt_uu, idx_cii, idx_cuu,
                                                vals_norm, vals_adj, vals_img_ii, vals_txt_ii,
                                                vals_img_uu, vals_txt_uu, vals_cii, vals_cuu,
                                                num_inters, cursor, colss, valss);

    // ---- CGE: 3 propagation layers; cge accumulation fused into epilogue ----
    concat_kernel<<<gdiv(n4_nodes, 256), 256>>>(user_emb, item_emb, egoA);
    unsigned gnodes = gdiv((long long)N_NODES * 16, 256);
    spmm1_kernel<<<gnodes, 256>>>(rowptr + RPO_NORM, colss + SEG_NORM, valss + SEG_NORM,
                                  egoA, egoB, cge, 1, N_NODES, 0);
    spmm1_kernel<<<gnodes, 256>>>(rowptr + RPO_NORM, colss + SEG_NORM, valss + SEG_NORM,
                                  egoB, egoA, cge, 2, N_NODES, 0);
    spmm1_kernel<<<gnodes, 256>>>(rowptr + RPO_NORM, colss + SEG_NORM, valss + SEG_NORM,
                                  egoA, egoB, cge, 2, N_NODES, 0);

    // ---- gating (dense GEMMs) ----
    unsigned gblk = gdiv(N_ITEMS, BM);
    gemm_kernel<<<gblk, 256>>>(image_feats, nullptr, trs_v, nullptr, nullptr, fv,   N_ITEMS, IMG_DIM, 0);
    gemm_kernel<<<gblk, 256>>>(fv, nullptr, gate_v,  bias_v,  fv, comv,  N_ITEMS, 64, 1);
    gemm_kernel<<<gblk, 256>>>(fv, comv,    gate1_v, bias1_v, fv, persv, N_ITEMS, 64, 1);
    gemm_kernel<<<gblk, 256>>>(text_feats, nullptr, trs_t, nullptr, nullptr, ft,   N_ITEMS, TXT_DIM, 0);
    gemm_kernel<<<gblk, 256>>>(ft, nullptr, gate_t,  bias_t,  ft, comt,  N_ITEMS, 64, 1);
    gemm_kernel<<<gblk, 256>>>(ft, comt,    gate1_t, bias1_t, ft, perst, N_ITEMS, 64, 1);

    // ---- adjacency SpMM fused over 4 channels (inv_u folded into uu vals) ----
    unsigned gusers = gdiv((long long)N_USERS * 16, 256);
    spmm4_kernel<<<gusers, 256>>>(rowptr + RPO_ADJ, colss + SEG_ADJ, valss + SEG_ADJ,
                                  persv, comv, perst, comt,
                                  upv, ucv, upt, uct, N_USERS);

    // ---- modal graph embeddings ----
    // user halves (uu graphs; colscale already folded into CSR vals)
    spmm1_kernel<<<gusers, 256>>>(rowptr + RPO_IMG_UU, colss + SEG_IMG_UU, valss + SEG_IMG_UU,
                                  upv, pev, nullptr, 0, N_USERS, 0);
    spmm1_kernel<<<gusers, 256>>>(rowptr + RPO_TXT_UU, colss + SEG_TXT_UU, valss + SEG_TXT_UU,
                                  upt, pet, nullptr, 0, N_USERS, 0);
    spmm2_kernel<<<gusers, 256>>>(rowptr + RPO_CUU, colss + SEG_CUU, valss + SEG_CUU,
                                  ucv, uct, cev, cet, N_USERS, 0);
    // item halves (ii graphs)
    spmm1_kernel<<<gusers, 256>>>(rowptr + RPO_IMG_II, colss + SEG_IMG_II, valss + SEG_IMG_II,
                                  persv, pev, nullptr, 0, N_ITEMS, N_USERS);
    spmm1_kernel<<<gusers, 256>>>(rowptr + RPO_TXT_II, colss + SEG_TXT_II, valss + SEG_TXT_II,
                                  perst, pet, nullptr, 0, N_ITEMS, N_USERS);
    spmm2_kernel<<<gusers, 256>>>(rowptr + RPO_CII, colss + SEG_CII, valss + SEG_CII,
                                  comv, comt, cev, cet, N_ITEMS, N_USERS);

    // ---- final fuse ----
    final_kernel<<<gdiv((long long)N_NODES * 32, 256), 256>>>(cge, pev, pet, cev, cet, att, out);
}